// round 1
// baseline (speedup 1.0000x reference)
#include <cuda_runtime.h>
#include <cuda_bf16.h>

// position_encoder: out[b,s,j] = x[b,s,j] + (j even ? sin : cos)(s / 10000^((j+1)/1024))
// B=4, S=8192, D=1024, fp32. Pure streaming add; pos computed on the fly via
// per-chunk accurate seed (fp64 arg -> sincosf) + fp32 rotation recurrence.

#define PE_S     8192
#define PE_D     1024
#define PE_B     4
#define PE_CHUNK 16
#define PE_D4    (PE_D / 4)      // 256 float4 groups per row

__global__ __launch_bounds__(256)
void position_encoder_kernel(const float4* __restrict__ x, float4* __restrict__ out) {
    const int d4 = threadIdx.x;              // 0..255 -> columns [4*d4, 4*d4+3]
    const int s0 = blockIdx.x * PE_CHUNK;    // chunk start row
    const int j0 = d4 * 4;

    // f_j = 10000^(-(j+1)/1024) = 2^(-(j+1) * log2(10000)/1024), computed in fp64
    const double kexp = 13.287712379549449 / 1024.0;   // log2(10000)/1024
    double fd[4];
    fd[0] = exp2(-(double)(j0 + 1) * kexp);
    const double r = exp2(-kexp);
    fd[1] = fd[0] * r;
    fd[2] = fd[1] * r;
    fd[3] = fd[2] * r;

    // Seed sin/cos at s0 (accurate sincosf on a tight fp32 argument),
    // plus per-step rotation coefficients sin(f), cos(f).
    float sn[4], cs[4], sf[4], cf[4];
#pragma unroll
    for (int c = 0; c < 4; c++) {
        double th = (double)s0 * fd[c];
        sincosf((float)th, &sn[c], &cs[c]);
        sincosf((float)fd[c], &sf[c], &cf[c]);
    }

    const size_t sstride = (size_t)PE_D4;                 // float4 per row
    const size_t bstride = (size_t)PE_S * PE_D4;          // float4 per batch
    const float4* __restrict__ xp = x   + (size_t)s0 * sstride + d4;
    float4* __restrict__       op = out + (size_t)s0 * sstride + d4;

#pragma unroll 4
    for (int k = 0; k < PE_CHUNK; k++) {
        // pos for columns j0..j0+3: even j -> sin, odd j -> cos
        const float4 p = make_float4(sn[0], cs[1], sn[2], cs[3]);
        const size_t row = (size_t)k * sstride;
#pragma unroll
        for (int b = 0; b < PE_B; b++) {
            const size_t idx = (size_t)b * bstride + row;
            float4 v = xp[idx];
            v.x += p.x; v.y += p.y; v.z += p.z; v.w += p.w;
            op[idx] = v;
        }
        // advance angle by f: sin(a+f) = s*cf + c*sf ; cos(a+f) = c*cf - s*sf
#pragma unroll
        for (int c = 0; c < 4; c++) {
            const float ns = fmaf(sn[c], cf[c],  cs[c] * sf[c]);
            const float nc = fmaf(cs[c], cf[c], -sn[c] * sf[c]);
            sn[c] = ns;
            cs[c] = nc;
        }
    }
}

extern "C" void kernel_launch(void* const* d_in, const int* in_sizes, int n_in,
                              void* d_out, int out_size) {
    (void)in_sizes; (void)n_in; (void)out_size;
    const float4* x = (const float4*)d_in[0];
    float4* out = (float4*)d_out;
    position_encoder_kernel<<<PE_S / PE_CHUNK, 256>>>(x, out);
}

// round 2
// speedup vs baseline: 1.1833x; 1.1833x over previous
#include <cuda_runtime.h>
#include <cuda_bf16.h>

// position_encoder: out[b,s,j] = x[b,s,j] + (j even ? sin : cos)(s / 10000^((j+1)/1024))
// B=4, S=8192, D=1024, fp32.
// Kernel 1 (setup): per-column constants fd_j (double), sin(fd_j), cos(fd_j).
// Kernel 2 (main): seed sin/cos at chunk start via fp64 arg + sincosf, then
// fp32 rotation recurrence; streaming add over 4 rows x 4 batches per block.

#define PE_S     8192
#define PE_D     1024
#define PE_B     4
#define PE_CHUNK 4
#define PE_D4    (PE_D / 4)

__device__ double g_fd[PE_D];
__device__ float  g_sf[PE_D];
__device__ float  g_cf[PE_D];

__global__ void pe_setup_kernel() {
    const int j = threadIdx.x;                     // 0..1023
    const double kexp = 13.287712379549449 / 1024.0;   // log2(10000)/1024
    const double fd = exp2(-(double)(j + 1) * kexp);
    g_fd[j] = fd;
    float s, c;
    sincosf((float)fd, &s, &c);
    g_sf[j] = s;
    g_cf[j] = c;
}

__global__ __launch_bounds__(256, 5)
void position_encoder_kernel(const float4* __restrict__ x, float4* __restrict__ out) {
    const int d4 = threadIdx.x;              // columns [4*d4, 4*d4+3]
    const int s0 = blockIdx.x * PE_CHUNK;
    const int j0 = d4 * 4;

    // Seed sin/cos at s0 (fp64 argument for accuracy) + rotation coefficients.
    float sn[4], cs[4], sf[4], cf[4];
#pragma unroll
    for (int c = 0; c < 4; c++) {
        const int jc = j0 + c;
        const double fd = g_fd[jc];
        sincosf((float)((double)s0 * fd), &sn[c], &cs[c]);
        sf[c] = g_sf[jc];
        cf[c] = g_cf[jc];
    }

    const size_t sstride = (size_t)PE_D4;
    const size_t bstride = (size_t)PE_S * PE_D4;
    const float4* __restrict__ xp = x   + (size_t)s0 * sstride + d4;
    float4* __restrict__       op = out + (size_t)s0 * sstride + d4;

#pragma unroll
    for (int k = 0; k < PE_CHUNK; k++) {
        const float4 p = make_float4(sn[0], cs[1], sn[2], cs[3]);
        const size_t row = (size_t)k * sstride;
#pragma unroll
        for (int b = 0; b < PE_B; b++) {
            const size_t idx = (size_t)b * bstride + row;
            float4 v = xp[idx];
            v.x += p.x; v.y += p.y; v.z += p.z; v.w += p.w;
            op[idx] = v;
        }
        // angle addition: advance by fd
#pragma unroll
        for (int c = 0; c < 4; c++) {
            const float ns = fmaf(sn[c], cf[c],  cs[c] * sf[c]);
            const float nc = fmaf(cs[c], cf[c], -sn[c] * sf[c]);
            sn[c] = ns;
            cs[c] = nc;
        }
    }
}

extern "C" void kernel_launch(void* const* d_in, const int* in_sizes, int n_in,
                              void* d_out, int out_size) {
    (void)in_sizes; (void)n_in; (void)out_size;
    const float4* x = (const float4*)d_in[0];
    float4* out = (float4*)d_out;
    pe_setup_kernel<<<1, PE_D>>>();
    position_encoder_kernel<<<PE_S / PE_CHUNK, 256>>>(x, out);
}